// round 12
// baseline (speedup 1.0000x reference)
#include <cuda_runtime.h>
#include <cstdint>

// Problem: out[N=100000,128] = zeros; out[i1]+=deltas[:,:128]; out[i2]+=deltas[:,128:256];
//          b = deltas[:,256:320].  d_out layout: [ out : N*128 fp32 ][ b : E*64 fp32 ]
//
// R11 = R3 structure exactly, but the deltas stream loads DROP the evict_first
// policy (R0, unhinted, sustained 6365 GB/s; every evict_first round only
// 5400-5977 GB/s — the hint appears to throttle fill handling). The evict_last
// pinning of out (zero-fill + bulk reduces) stays — that's what cut total bytes
// from 1162MB to 871MB. Stream loads instead get the L2::256B fetch-size hint.

#define WARPS_PER_BLOCK 8
#define THREADS_PER_BLOCK (WARPS_PER_BLOCK * 32)
#define GRID_BLOCKS 2048

__device__ __forceinline__ uint64_t make_evict_last_policy() {
    uint64_t pol;
    asm("createpolicy.fractional.L2::evict_last.b64 %0, 1.0;" : "=l"(pol));
    return pol;
}

__global__ void zero_out_kernel(float4* __restrict__ out4, long n4) {
    long i = blockIdx.x * (long)blockDim.x + threadIdx.x;
    if (i < n4) {
        uint64_t pol = make_evict_last_policy();
        asm volatile("st.global.L2::cache_hint.v4.f32 [%0], {%1,%2,%3,%4}, %5;"
                     :: "l"(out4 + i), "f"(0.f), "f"(0.f), "f"(0.f), "f"(0.f), "l"(pol)
                     : "memory");
    }
}

__device__ __forceinline__ float4 ldg_nc256(const float4* p) {
    float4 v;
    asm("ld.global.nc.L2::256B.v4.f32 {%0,%1,%2,%3}, [%4];"
        : "=f"(v.x), "=f"(v.y), "=f"(v.z), "=f"(v.w) : "l"(p));
    return v;
}

__device__ __forceinline__ void stg_stream(float4* p, float4 v) {
    asm volatile("st.global.cs.v4.f32 [%0], {%1,%2,%3,%4};"
                 :: "l"(p), "f"(v.x), "f"(v.y), "f"(v.z), "f"(v.w)
                 : "memory");
}

__device__ __forceinline__ void bulk_reduce_add_f32(float* gdst, uint32_t ssrc,
                                                    uint32_t bytes, uint64_t pol) {
    asm volatile(
        "cp.reduce.async.bulk.global.shared::cta.bulk_group.L2::cache_hint.add.f32 "
        "[%0], [%1], %2, %3;"
        :: "l"(gdst), "r"(ssrc), "r"(bytes), "l"(pol)
        : "memory");
}

__global__ void __launch_bounds__(THREADS_PER_BLOCK, 8)
scatter_kernel(const float4* __restrict__ deltas4,  // E * 80 float4
               const int*    __restrict__ i1,       // E
               const int*    __restrict__ i2,       // E
               float*        __restrict__ out,      // N * 128 fp32
               float4*       __restrict__ bout4,    // E * 16 float4
               long E, long nwarps)
{
    // Per-warp double buffer: 2 x 64 float4 = 2 KB/warp, 16 KB/block.
    __shared__ __align__(16) float4 buf[WARPS_PER_BLOCK][2][64];

    const int wid  = threadIdx.x >> 5;
    const int lane = threadIdx.x & 31;
    const long gw  = (long)blockIdx.x * WARPS_PER_BLOCK + wid;

    const uint64_t pol_el = make_evict_last_policy();

    int parity = 0;
    for (long e = gw; e < E; e += nwarps, parity ^= 1) {
        // Reclaim this parity's buffer (handed to TMA 2 iterations ago).
        if (lane == 0)
            asm volatile("cp.async.bulk.wait_group.read 1;" ::: "memory");
        __syncwarp();

        const float4* row = deltas4 + e * 80;

        // ux: chunks [0,32) ; uy: chunks [32,64) -> SMEM (coalesced)
        float4 v0 = ldg_nc256(row + lane);
        float4 v1 = ldg_nc256(row + 32 + lane);
        buf[wid][parity][lane]      = v0;
        buf[wid][parity][32 + lane] = v1;

        // b: chunks [64,80) -> straight to output, bypass SMEM
        if (lane < 16) {
            float4 vb = ldg_nc256(row + 64 + lane);
            stg_stream(bout4 + e * 16 + lane, vb);
        }
        __syncwarp();

        if (lane == 0) {
            asm volatile("fence.proxy.async.shared::cta;" ::: "memory");
            int r1 = __ldg(&i1[e]);
            int r2 = __ldg(&i2[e]);
            uint32_t s = (uint32_t)__cvta_generic_to_shared(&buf[wid][parity][0]);
            bulk_reduce_add_f32(out + (long)r1 * 128, s,       512, pol_el);
            bulk_reduce_add_f32(out + (long)r2 * 128, s + 512, 512, pol_el);
            asm volatile("cp.async.bulk.commit_group;" ::: "memory");
        }
    }

    // Drain all pending bulk groups before exit.
    if (lane == 0)
        asm volatile("cp.async.bulk.wait_group 0;" ::: "memory");
}

extern "C" void kernel_launch(void* const* d_in, const int* in_sizes, int n_in,
                              void* d_out, int out_size)
{
    // metadata order: unary(N*128 f32), binary(E*64 f32), deltas(E*320 f32),
    //                 index1(E i32), index2(E i32)
    const long N = in_sizes[0] / 128;
    const long E = in_sizes[2] / 320;

    const float4* deltas4 = (const float4*)d_in[2];
    const int*    i1      = (const int*)d_in[3];
    const int*    i2      = (const int*)d_in[4];

    float*  out   = (float*)d_out;                       // N*128
    float4* bout4 = (float4*)((float*)d_out + N * 128);  // E*16 float4

    // 1) zero the scatter target and pin it in L2 (evict_last)
    {
        long n4 = (N * 128) / 4;
        int  threads = 256;
        long blocks = (n4 + threads - 1) / threads;
        zero_out_kernel<<<(unsigned)blocks, threads>>>((float4*)out, n4);
    }

    // 2) scatter-add (TMA bulk-reduce) + b copy
    {
        long nwarps = (long)GRID_BLOCKS * WARPS_PER_BLOCK;
        scatter_kernel<<<GRID_BLOCKS, THREADS_PER_BLOCK>>>(deltas4, i1, i2, out, bout4, E, nwarps);
    }
}

// round 13
// speedup vs baseline: 1.1781x; 1.1781x over previous
#include <cuda_runtime.h>
#include <cstdint>

// Problem: out[N=100000,128] = zeros; out[i1]+=deltas[:,:128]; out[i2]+=deltas[:,128:256];
//          b = deltas[:,256:320].  d_out layout: [ out : N*128 fp32 ][ b : E*64 fp32 ]
//
// R12 = R3 + composed load hints. Round isolation showed:
//   evict_first policy on the deltas stream  -> out stays L2-resident (871 MB vs 1132 MB)
//   L2::256B fetch granularity               -> 6.57 TB/s achieved DRAM rate (vs 5.9)
// This round combines them on the same load: ld.global.nc.L2::cache_hint.L2::256B
// with an evict_first policy register. Reduce path (TMA bulk reduce, evict_last)
// and structure identical to R3 (best: 145.7us scatter).

#define WARPS_PER_BLOCK 8
#define THREADS_PER_BLOCK (WARPS_PER_BLOCK * 32)
#define GRID_BLOCKS 2048

__device__ __forceinline__ uint64_t make_evict_last_policy() {
    uint64_t pol;
    asm("createpolicy.fractional.L2::evict_last.b64 %0, 1.0;" : "=l"(pol));
    return pol;
}

__device__ __forceinline__ uint64_t make_evict_first_policy() {
    uint64_t pol;
    asm("createpolicy.fractional.L2::evict_first.b64 %0, 1.0;" : "=l"(pol));
    return pol;
}

__global__ void zero_out_kernel(float4* __restrict__ out4, long n4) {
    long i = blockIdx.x * (long)blockDim.x + threadIdx.x;
    if (i < n4) {
        uint64_t pol = make_evict_last_policy();
        asm volatile("st.global.L2::cache_hint.v4.f32 [%0], {%1,%2,%3,%4}, %5;"
                     :: "l"(out4 + i), "f"(0.f), "f"(0.f), "f"(0.f), "f"(0.f), "l"(pol)
                     : "memory");
    }
}

__device__ __forceinline__ float4 ldg_stream256(const float4* p, uint64_t pol) {
    float4 v;
    asm("ld.global.nc.L2::cache_hint.L2::256B.v4.f32 {%0,%1,%2,%3}, [%4], %5;"
        : "=f"(v.x), "=f"(v.y), "=f"(v.z), "=f"(v.w) : "l"(p), "l"(pol));
    return v;
}

__device__ __forceinline__ void stg_stream(float4* p, float4 v) {
    asm volatile("st.global.cs.v4.f32 [%0], {%1,%2,%3,%4};"
                 :: "l"(p), "f"(v.x), "f"(v.y), "f"(v.z), "f"(v.w)
                 : "memory");
}

__device__ __forceinline__ void bulk_reduce_add_f32(float* gdst, uint32_t ssrc,
                                                    uint32_t bytes, uint64_t pol) {
    asm volatile(
        "cp.reduce.async.bulk.global.shared::cta.bulk_group.L2::cache_hint.add.f32 "
        "[%0], [%1], %2, %3;"
        :: "l"(gdst), "r"(ssrc), "r"(bytes), "l"(pol)
        : "memory");
}

__global__ void __launch_bounds__(THREADS_PER_BLOCK, 8)
scatter_kernel(const float4* __restrict__ deltas4,  // E * 80 float4
               const int*    __restrict__ i1,       // E
               const int*    __restrict__ i2,       // E
               float*        __restrict__ out,      // N * 128 fp32
               float4*       __restrict__ bout4,    // E * 16 float4
               long E, long nwarps)
{
    // Per-warp double buffer: 2 x 64 float4 = 2 KB/warp, 16 KB/block.
    __shared__ __align__(16) float4 buf[WARPS_PER_BLOCK][2][64];

    const int wid  = threadIdx.x >> 5;
    const int lane = threadIdx.x & 31;
    const long gw  = (long)blockIdx.x * WARPS_PER_BLOCK + wid;

    const uint64_t pol_ef = make_evict_first_policy();
    const uint64_t pol_el = make_evict_last_policy();

    int parity = 0;
    for (long e = gw; e < E; e += nwarps, parity ^= 1) {
        // Reclaim this parity's buffer (handed to TMA 2 iterations ago).
        if (lane == 0)
            asm volatile("cp.async.bulk.wait_group.read 1;" ::: "memory");
        __syncwarp();

        const float4* row = deltas4 + e * 80;

        // ux: chunks [0,32) ; uy: chunks [32,64) -> SMEM (coalesced)
        float4 v0 = ldg_stream256(row + lane,      pol_ef);
        float4 v1 = ldg_stream256(row + 32 + lane, pol_ef);
        buf[wid][parity][lane]      = v0;
        buf[wid][parity][32 + lane] = v1;

        // b: chunks [64,80) -> straight to output, bypass SMEM
        if (lane < 16) {
            float4 vb = ldg_stream256(row + 64 + lane, pol_ef);
            stg_stream(bout4 + e * 16 + lane, vb);
        }
        __syncwarp();

        if (lane == 0) {
            asm volatile("fence.proxy.async.shared::cta;" ::: "memory");
            int r1 = __ldg(&i1[e]);
            int r2 = __ldg(&i2[e]);
            uint32_t s = (uint32_t)__cvta_generic_to_shared(&buf[wid][parity][0]);
            bulk_reduce_add_f32(out + (long)r1 * 128, s,       512, pol_el);
            bulk_reduce_add_f32(out + (long)r2 * 128, s + 512, 512, pol_el);
            asm volatile("cp.async.bulk.commit_group;" ::: "memory");
        }
    }

    // Drain all pending bulk groups before exit.
    if (lane == 0)
        asm volatile("cp.async.bulk.wait_group 0;" ::: "memory");
}

extern "C" void kernel_launch(void* const* d_in, const int* in_sizes, int n_in,
                              void* d_out, int out_size)
{
    // metadata order: unary(N*128 f32), binary(E*64 f32), deltas(E*320 f32),
    //                 index1(E i32), index2(E i32)
    const long N = in_sizes[0] / 128;
    const long E = in_sizes[2] / 320;

    const float4* deltas4 = (const float4*)d_in[2];
    const int*    i1      = (const int*)d_in[3];
    const int*    i2      = (const int*)d_in[4];

    float*  out   = (float*)d_out;                       // N*128
    float4* bout4 = (float4*)((float*)d_out + N * 128);  // E*16 float4

    // 1) zero the scatter target and pin it in L2 (evict_last)
    {
        long n4 = (N * 128) / 4;
        int  threads = 256;
        long blocks = (n4 + threads - 1) / threads;
        zero_out_kernel<<<(unsigned)blocks, threads>>>((float4*)out, n4);
    }

    // 2) scatter-add (TMA bulk-reduce) + b copy
    {
        long nwarps = (long)GRID_BLOCKS * WARPS_PER_BLOCK;
        scatter_kernel<<<GRID_BLOCKS, THREADS_PER_BLOCK>>>(deltas4, i1, i2, out, bout4, E, nwarps);
    }
}